// round 10
// baseline (speedup 1.0000x reference)
#include <cuda_runtime.h>
#include <cuda_fp16.h>
#include <cstdint>

// ============================================================
// Problem constants
// ============================================================
#define BN   4
#define CN   16
#define HN   512
#define WN   512
#define HID  128
#define TILE 128      // pixels per row-tile; CTA = 2 rows x 128 px = 256 M-rows

// SMEM (byte offsets). Total 47872 B -> 4 CTAs/SM (191.5 KB).
#define SM_A     0          // A: 256 rows x 112 B (f16 x 48); later aliased as update stage
#define PITCH_A  112
#define SM_W0    28672      // w0: 128 rows x 112 B (f16 x 48)
#define PITCH_W0 112
#define SM_W1    43008      // w1: 16 rows x 272 B (f16 x 128)
#define PITCH_W1 272
#define SM_BIAS  47360      // b0: 128 f32
#define SM_TOTAL 47872

// ============================================================
// PTX helpers (base sm_103-compatible: ldmatrix + mma.sync)
// ============================================================
__device__ __forceinline__ uint32_t smem_u32(const void* p) {
    uint32_t a;
    asm("{ .reg .u64 t; cvta.to.shared.u64 t, %1; cvt.u32.u64 %0, t; }"
        : "=r"(a) : "l"(p));
    return a;
}

__device__ __forceinline__ void ldsm_x4(uint32_t* r, uint32_t addr) {
    asm volatile("ldmatrix.sync.aligned.m8n8.x4.shared.b16 {%0,%1,%2,%3}, [%4];"
                 : "=r"(r[0]), "=r"(r[1]), "=r"(r[2]), "=r"(r[3]) : "r"(addr));
}

// D += A * B  (m16n8k16, f16 in, f32 accum)
__device__ __forceinline__ void mma16816(float* c, const uint32_t* a,
                                         uint32_t b0, uint32_t b1) {
    asm volatile("mma.sync.aligned.m16n8k16.row.col.f32.f16.f16.f32 "
                 "{%0,%1,%2,%3}, {%4,%5,%6,%7}, {%8,%9}, {%0,%1,%2,%3};"
                 : "+f"(c[0]), "+f"(c[1]), "+f"(c[2]), "+f"(c[3])
                 : "r"(a[0]), "r"(a[1]), "r"(a[2]), "r"(a[3]),
                   "r"(b0), "r"(b1));
}

__device__ __forceinline__ uint32_t pack2(float a, float b) {
    __half2 h = __floats2half2_rn(a, b);
    return *reinterpret_cast<uint32_t*>(&h);
}

// pack to f16x2 then relu in f16 (HMNMX2): identical to relu-then-cvt
__device__ __forceinline__ uint32_t packrelu2(float a, float b) {
    __half2 h = __floats2half2_rn(a, b);
    h = __hmax2(h, __half2half2(__ushort_as_half(0)));
    return *reinterpret_cast<uint32_t*>(&h);
}

// ============================================================
// Kernel: one CTA = 2 adjacent image rows x 128 pixels.
// 4 CTAs/SM (64-reg budget): A fragments re-loaded per hidden chunk
// instead of hoisted, trading cheap L1 traffic for occupancy.
// ============================================================
__global__ void __launch_bounds__(256, 4) ca_mlp_kernel(
    const float* __restrict__ x,
    const float* __restrict__ w0,
    const float* __restrict__ b0,
    const float* __restrict__ w1,
    const float* __restrict__ ru,
    float* __restrict__ out)
{
    extern __shared__ char smem[];
    const uint32_t sbase = smem_u32(smem);

    const int tid  = threadIdx.x;
    const int warp = tid >> 5;
    const int lane = tid & 31;

    const int bx   = blockIdx.x;
    const int wt   = bx & 3;                 // column tile
    const int hblk = (bx >> 2) & 255;        // row pair
    const int bb   = bx >> 10;               // batch
    const int h0   = hblk * 2;
    const int wpix = wt * TILE;

    // ---------------- Load weights / bias to SMEM ----------------
    // w0: [128][48] f16
    for (int idx = tid; idx < 128 * 24; idx += 256) {
        const int o = idx / 24;
        const int k = (idx - o * 24) * 2;
        *reinterpret_cast<uint32_t*>(smem + SM_W0 + o * PITCH_W0 + k * 2) =
            pack2(w0[o * 48 + k], w0[o * 48 + k + 1]);
    }
    // w1: [16][128] f16
    for (int idx = tid; idx < 16 * 64; idx += 256) {
        const int o = idx >> 6;
        const int k = (idx & 63) * 2;
        *reinterpret_cast<uint32_t*>(smem + SM_W1 + o * PITCH_W1 + k * 2) =
            pack2(w1[o * 128 + k], w1[o * 128 + k + 1]);
    }
    // bias f32
    if (tid < 128)
        *reinterpret_cast<float*>(smem + SM_BIAS + tid * 4) = b0[tid];

    // ---------------- Phase 1: Sobel from gmem -> registers -> SMEM A ----------------
    {
        const int g8   = tid >> 7;           // channel half (0: ch 0-7, 1: ch 8-15)
        const int pcol = tid & 127;          // column within tile
        const int P    = wpix + pcol;        // global column
        const int c0   = g8 * 8;

        // row validity (rows h0-1 .. h0+2)
        const bool r0ok = (h0 - 1) >= 0;
        const bool r3ok = (h0 + 2) < HN;

        const bool isL = (lane == 0);
        const bool isR = (lane == 31);
        const int  Pe  = isL ? (P - 1) : (P + 1);
        const bool peok = (isL || isR) && ((unsigned)Pe < (unsigned)WN);

        // feature accumulators: [xv|gx|gy] x 4 packed pairs, top & bottom rows
        uint32_t ft[3][4], fb[3][4];

        #pragma unroll
        for (int cp = 0; cp < 4; cp++) {
            float xvt[2], xvb[2], gxt[2], gxb[2], gyt[2], gyb[2];
            #pragma unroll
            for (int e = 0; e < 2; e++) {
                const int c = c0 + cp * 2 + e;
                const float* base = x + (((size_t)bb * CN + c) * HN) * WN;
                const float* col  = base + (size_t)(h0 - 1) * WN + P;
                const float x0 = r0ok ? col[0]          : 0.0f;
                const float x1 =        col[WN];
                const float x2 =        col[2 * WN];
                const float x3 = r3ok ? col[3 * WN]     : 0.0f;

                const float s0 = x0 + 2.0f * x1 + x2;
                const float s1 = x1 + 2.0f * x2 + x3;
                const float d0 = x2 - x0;
                const float d1 = x3 - x1;

                // edge column (lane 0 -> P-1, lane 31 -> P+1), zero-padded
                float se0 = 0.0f, se1 = 0.0f, de0 = 0.0f, de1 = 0.0f;
                if (peok) {
                    const float* ecol = base + (size_t)(h0 - 1) * WN + Pe;
                    const float e0 = r0ok ? ecol[0]      : 0.0f;
                    const float e1 =        ecol[WN];
                    const float e2 =        ecol[2 * WN];
                    const float e3 = r3ok ? ecol[3 * WN] : 0.0f;
                    se0 = e0 + 2.0f * e1 + e2;
                    se1 = e1 + 2.0f * e2 + e3;
                    de0 = e2 - e0;
                    de1 = e3 - e1;
                }

                float sl0 = __shfl_up_sync(0xffffffffu, s0, 1);
                float sl1 = __shfl_up_sync(0xffffffffu, s1, 1);
                float dl0 = __shfl_up_sync(0xffffffffu, d0, 1);
                float dl1 = __shfl_up_sync(0xffffffffu, d1, 1);
                float sr0 = __shfl_down_sync(0xffffffffu, s0, 1);
                float sr1 = __shfl_down_sync(0xffffffffu, s1, 1);
                float dr0 = __shfl_down_sync(0xffffffffu, d0, 1);
                float dr1 = __shfl_down_sync(0xffffffffu, d1, 1);
                if (isL) { sl0 = se0; sl1 = se1; dl0 = de0; dl1 = de1; }
                if (isR) { sr0 = se0; sr1 = se1; dr0 = de0; dr1 = de1; }

                xvt[e] = x1;
                xvb[e] = x2;
                gxt[e] = sr0 - sl0;
                gxb[e] = sr1 - sl1;
                gyt[e] = dl0 + 2.0f * d0 + dr0;
                gyb[e] = dl1 + 2.0f * d1 + dr1;
            }
            ft[0][cp] = pack2(xvt[0], xvt[1]);
            ft[1][cp] = pack2(gxt[0], gxt[1]);
            ft[2][cp] = pack2(gyt[0], gyt[1]);
            fb[0][cp] = pack2(xvb[0], xvb[1]);
            fb[1][cp] = pack2(gxb[0], gxb[1]);
            fb[2][cp] = pack2(gyb[0], gyb[1]);
        }

        // Conflict-free STS.128: 112 B stride -> quad index 7*lane mod 8, distinct
        char* rowt = smem + SM_A + pcol * PITCH_A;          // M-row = pcol (row h0)
        char* rowb = smem + SM_A + (128 + pcol) * PITCH_A;  // M-row = 128+pcol (row h0+1)
        #pragma unroll
        for (int f = 0; f < 3; f++) {
            *reinterpret_cast<uint4*>(rowt + f * 32 + c0 * 2) =
                make_uint4(ft[f][0], ft[f][1], ft[f][2], ft[f][3]);
            *reinterpret_cast<uint4*>(rowb + f * 32 + c0 * 2) =
                make_uint4(fb[f][0], fb[f][1], fb[f][2], fb[f][3]);
        }
    }
    __syncthreads();

    // ---------------- Phase 2: fused MLP (per warp: 32 M-rows) ----------------
    const int m0 = warp * 32;
    const int t  = lane & 3;
    const int g  = lane >> 2;

    float c2[2][2][4];
    #pragma unroll
    for (int mt = 0; mt < 2; mt++)
        #pragma unroll
        for (int n2 = 0; n2 < 2; n2++)
            #pragma unroll
            for (int j = 0; j < 4; j++) c2[mt][n2][j] = 0.0f;

    #pragma unroll
    for (int hcj = 0; hcj < 8; hcj++) {       // 16 hidden units per chunk
        // bias init (fp32 exact): cols hcj*16 + nt*8 + t*2 + {0,1}
        float c1[2][2][4];
        #pragma unroll
        for (int nt = 0; nt < 2; nt++) {
            const float2 b = *reinterpret_cast<const float2*>(
                smem + SM_BIAS + (hcj * 16 + nt * 8 + t * 2) * 4);
            #pragma unroll
            for (int mt = 0; mt < 2; mt++) {
                c1[nt][mt][0] = b.x; c1[nt][mt][1] = b.y;
                c1[nt][mt][2] = b.x; c1[nt][mt][3] = b.y;
            }
        }

        #pragma unroll
        for (int kt = 0; kt < 3; kt++) {
            // A fragments re-loaded per chunk (64-reg budget; L1 has headroom)
            uint32_t afr0[4], afr1[4];
            const uint32_t acol = kt * 32 + ((lane >> 4) << 4);
            ldsm_x4(afr0, sbase + SM_A + (m0 + (lane & 15)) * PITCH_A + acol);
            ldsm_x4(afr1, sbase + SM_A + (m0 + 16 + (lane & 15)) * PITCH_A + acol);

            // One ldsm_x4 over W0 rows [hcj*16,+16), k-cols [kt*16,+16):
            //   nt=0 frag = {bfr[0], bfr[2]}, nt=1 frag = {bfr[1], bfr[3]}
            uint32_t bfr[4];
            ldsm_x4(bfr, sbase + SM_W0 + (hcj * 16 + (lane & 15)) * PITCH_W0
                         + kt * 32 + ((lane >> 4) << 4));
            mma16816(c1[0][0], afr0, bfr[0], bfr[2]);
            mma16816(c1[0][1], afr1, bfr[0], bfr[2]);
            mma16816(c1[1][0], afr0, bfr[1], bfr[3]);
            mma16816(c1[1][1], afr1, bfr[1], bfr[3]);
        }

        // layer 2: one ldsm_x4 over W1 rows 0-15, k-cols [hcj*16*2 .. +16)
        uint32_t wfr[4];
        ldsm_x4(wfr, sbase + SM_W1 + (lane & 15) * PITCH_W1
                     + hcj * 32 + ((lane >> 4) << 4));
        #pragma unroll
        for (int mt = 0; mt < 2; mt++) {
            uint32_t a2[4];
            a2[0] = packrelu2(c1[0][mt][0], c1[0][mt][1]);
            a2[1] = packrelu2(c1[0][mt][2], c1[0][mt][3]);
            a2[2] = packrelu2(c1[1][mt][0], c1[1][mt][1]);
            a2[3] = packrelu2(c1[1][mt][2], c1[1][mt][3]);
            mma16816(c2[mt][0], a2, wfr[0], wfr[2]);
            mma16816(c2[mt][1], a2, wfr[1], wfr[3]);
        }
    }

    // ---------------- Stage update into A region (per-warp rows, safe alias) ----------------
    {
        #pragma unroll
        for (int mt = 0; mt < 2; mt++)
            #pragma unroll
            for (int n2 = 0; n2 < 2; n2++) {
                const int r0 = m0 + mt * 16 + g;
                const int col = n2 * 8 + t * 2;
                float* p0 = reinterpret_cast<float*>(smem + SM_A + r0 * PITCH_A);
                float* p1 = reinterpret_cast<float*>(smem + SM_A + (r0 + 8) * PITCH_A);
                p0[col]     = c2[mt][n2][0];
                p0[col + 1] = c2[mt][n2][1];
                p1[col]     = c2[mt][n2][2];
                p1[col + 1] = c2[mt][n2][3];
            }
    }
    __syncthreads();

    // ---------------- Phase 3: epilogue out = x + update * mask ----------------
    {
        const int r = tid >> 7;
        const int p = tid & 127;
        const int h = h0 + r;
        const float u = ru[((size_t)bb * HN + h) * WN + wpix + p];
        const float m = (u > 0.5f) ? 1.0f : 0.0f;

        // Conflict-free LDS.128: 4 x uint4 covers the 16 update floats
        const float4* updq = reinterpret_cast<const float4*>(smem + SM_A + tid * PITCH_A);
        float upd[16];
        #pragma unroll
        for (int q = 0; q < 4; q++) {
            const float4 v = updq[q];
            upd[4 * q]     = v.x;
            upd[4 * q + 1] = v.y;
            upd[4 * q + 2] = v.z;
            upd[4 * q + 3] = v.w;
        }
        #pragma unroll
        for (int c = 0; c < CN; c++) {
            const size_t gi = (((size_t)bb * CN + c) * HN + h) * WN + wpix + p;
            out[gi] = x[gi] + upd[c] * m;
        }
    }
}

// ============================================================
// Launch
// ============================================================
extern "C" void kernel_launch(void* const* d_in, const int* in_sizes, int n_in,
                              void* d_out, int out_size) {
    (void)in_sizes; (void)n_in; (void)out_size;
    const float* x  = (const float*)d_in[0];
    const float* w0 = (const float*)d_in[1];
    const float* b0 = (const float*)d_in[2];
    const float* w1 = (const float*)d_in[3];
    const float* ru = (const float*)d_in[4];
    float* out = (float*)d_out;

    const int grid = BN * (HN / 2) * (WN / TILE);   // 4096
    ca_mlp_kernel<<<grid, 256, SM_TOTAL>>>(x, w0, b0, w1, ru, out);
}

// round 11
// speedup vs baseline: 1.1544x; 1.1544x over previous
#include <cuda_runtime.h>
#include <cuda_fp16.h>
#include <cstdint>

// ============================================================
// Problem constants
// ============================================================
#define BN   4
#define CN   16
#define HN   512
#define WN   512
#define HID  128
#define TILE 128      // pixels per row-tile; CTA = 2 rows x 128 px = 256 M-rows

// SMEM (byte offsets). Total 64512 B -> 3 CTAs/SM (193.5 KB <= 228 KB).
#define SM_A     0          // A: 256 rows x 112 B (f16 x 48)
#define PITCH_A  112
#define SM_W0    28672      // w0: 128 rows x 112 B (f16 x 48)
#define PITCH_W0 112
#define SM_W1    43008      // w1: 16 rows x 272 B (f16 x 128)
#define PITCH_W1 272
#define SM_BIAS  47360      // b0: 128 f32
#define SM_UPD   47872      // update stage: 16 ch x 260 f32 (pad) = 16640
#define UPD_PITCH 260       // floats per channel row (128*2 px + pad)
#define SM_TOTAL 64512

// ============================================================
// PTX helpers (base sm_103-compatible: ldmatrix + mma.sync)
// ============================================================
__device__ __forceinline__ uint32_t smem_u32(const void* p) {
    uint32_t a;
    asm("{ .reg .u64 t; cvta.to.shared.u64 t, %1; cvt.u32.u64 %0, t; }"
        : "=r"(a) : "l"(p));
    return a;
}

__device__ __forceinline__ void ldsm_x4(uint32_t* r, uint32_t addr) {
    asm volatile("ldmatrix.sync.aligned.m8n8.x4.shared.b16 {%0,%1,%2,%3}, [%4];"
                 : "=r"(r[0]), "=r"(r[1]), "=r"(r[2]), "=r"(r[3]) : "r"(addr));
}

// D += A * B  (m16n8k16, f16 in, f32 accum)
__device__ __forceinline__ void mma16816(float* c, const uint32_t* a,
                                         uint32_t b0, uint32_t b1) {
    asm volatile("mma.sync.aligned.m16n8k16.row.col.f32.f16.f16.f32 "
                 "{%0,%1,%2,%3}, {%4,%5,%6,%7}, {%8,%9}, {%0,%1,%2,%3};"
                 : "+f"(c[0]), "+f"(c[1]), "+f"(c[2]), "+f"(c[3])
                 : "r"(a[0]), "r"(a[1]), "r"(a[2]), "r"(a[3]),
                   "r"(b0), "r"(b1));
}

// D = A * B + {cx,cy,cx,cy}  — initializes accumulator with broadcast bias
// (c-frag lanes hold cols t*2,t*2+1 in elems {0,2} resp {1,3})
__device__ __forceinline__ void mma16816_init(float* d, const uint32_t* a,
                                              uint32_t b0, uint32_t b1,
                                              float cx, float cy) {
    asm volatile("mma.sync.aligned.m16n8k16.row.col.f32.f16.f16.f32 "
                 "{%0,%1,%2,%3}, {%4,%5,%6,%7}, {%8,%9}, {%10,%11,%10,%11};"
                 : "=&f"(d[0]), "=&f"(d[1]), "=&f"(d[2]), "=&f"(d[3])
                 : "r"(a[0]), "r"(a[1]), "r"(a[2]), "r"(a[3]),
                   "r"(b0), "r"(b1), "f"(cx), "f"(cy));
}

__device__ __forceinline__ uint32_t pack2(float a, float b) {
    __half2 h = __floats2half2_rn(a, b);
    return *reinterpret_cast<uint32_t*>(&h);
}

// pack to f16x2 then relu in f16 (HMNMX2): identical to relu-then-cvt
__device__ __forceinline__ uint32_t packrelu2(float a, float b) {
    __half2 h = __floats2half2_rn(a, b);
    h = __hmax2(h, __half2half2(__ushort_as_half(0)));
    return *reinterpret_cast<uint32_t*>(&h);
}

// ============================================================
// Kernel: one CTA = 2 adjacent image rows x 128 pixels (256 M-rows).
// Phase 1: separable Sobel from gmem, shfl horizontal; features -> SMEM A.
// Phase 2: fused 2-layer MLP per warp; bias injected via MMA C-operand.
// Phase 3: update staged [ch][px] -> fully vectorized float4 epilogue.
// ============================================================
__global__ void __launch_bounds__(256, 3) ca_mlp_kernel(
    const float* __restrict__ x,
    const float* __restrict__ w0,
    const float* __restrict__ b0,
    const float* __restrict__ w1,
    const float* __restrict__ ru,
    float* __restrict__ out)
{
    extern __shared__ char smem[];
    const uint32_t sbase = smem_u32(smem);

    const int tid  = threadIdx.x;
    const int warp = tid >> 5;
    const int lane = tid & 31;

    const int bx   = blockIdx.x;
    const int wt   = bx & 3;                 // column tile
    const int hblk = (bx >> 2) & 255;        // row pair
    const int bb   = bx >> 10;               // batch
    const int h0   = hblk * 2;
    const int wpix = wt * TILE;

    // ---------------- Load weights / bias to SMEM ----------------
    // w0: [128][48] f16
    for (int idx = tid; idx < 128 * 24; idx += 256) {
        const int o = idx / 24;
        const int k = (idx - o * 24) * 2;
        *reinterpret_cast<uint32_t*>(smem + SM_W0 + o * PITCH_W0 + k * 2) =
            pack2(w0[o * 48 + k], w0[o * 48 + k + 1]);
    }
    // w1: [16][128] f16
    for (int idx = tid; idx < 16 * 64; idx += 256) {
        const int o = idx >> 6;
        const int k = (idx & 63) * 2;
        *reinterpret_cast<uint32_t*>(smem + SM_W1 + o * PITCH_W1 + k * 2) =
            pack2(w1[o * 128 + k], w1[o * 128 + k + 1]);
    }
    // bias f32
    if (tid < 128)
        *reinterpret_cast<float*>(smem + SM_BIAS + tid * 4) = b0[tid];

    // ---------------- Phase 1: Sobel from gmem -> registers -> SMEM A ----------------
    {
        const int g8   = tid >> 7;           // channel half (0: ch 0-7, 1: ch 8-15)
        const int pcol = tid & 127;          // column within tile
        const int P    = wpix + pcol;        // global column
        const int c0   = g8 * 8;

        // row validity (rows h0-1 .. h0+2)
        const bool r0ok = (h0 - 1) >= 0;
        const bool r3ok = (h0 + 2) < HN;

        const bool isL = (lane == 0);
        const bool isR = (lane == 31);
        const int  Pe  = isL ? (P - 1) : (P + 1);
        const bool peok = (isL || isR) && ((unsigned)Pe < (unsigned)WN);

        // feature accumulators: [xv|gx|gy] x 4 packed pairs, top & bottom rows
        uint32_t ft[3][4], fb[3][4];

        #pragma unroll
        for (int cp = 0; cp < 4; cp++) {
            float xvt[2], xvb[2], gxt[2], gxb[2], gyt[2], gyb[2];
            #pragma unroll
            for (int e = 0; e < 2; e++) {
                const int c = c0 + cp * 2 + e;
                const float* base = x + (((size_t)bb * CN + c) * HN) * WN;
                const float* col  = base + (size_t)(h0 - 1) * WN + P;
                const float x0 = r0ok ? col[0]          : 0.0f;
                const float x1 =        col[WN];
                const float x2 =        col[2 * WN];
                const float x3 = r3ok ? col[3 * WN]     : 0.0f;

                const float s0 = x0 + 2.0f * x1 + x2;
                const float s1 = x1 + 2.0f * x2 + x3;
                const float d0 = x2 - x0;
                const float d1 = x3 - x1;

                // edge column (lane 0 -> P-1, lane 31 -> P+1), zero-padded
                float se0 = 0.0f, se1 = 0.0f, de0 = 0.0f, de1 = 0.0f;
                if (peok) {
                    const float* ecol = base + (size_t)(h0 - 1) * WN + Pe;
                    const float e0 = r0ok ? ecol[0]      : 0.0f;
                    const float e1 =        ecol[WN];
                    const float e2 =        ecol[2 * WN];
                    const float e3 = r3ok ? ecol[3 * WN] : 0.0f;
                    se0 = e0 + 2.0f * e1 + e2;
                    se1 = e1 + 2.0f * e2 + e3;
                    de0 = e2 - e0;
                    de1 = e3 - e1;
                }

                float sl0 = __shfl_up_sync(0xffffffffu, s0, 1);
                float sl1 = __shfl_up_sync(0xffffffffu, s1, 1);
                float dl0 = __shfl_up_sync(0xffffffffu, d0, 1);
                float dl1 = __shfl_up_sync(0xffffffffu, d1, 1);
                float sr0 = __shfl_down_sync(0xffffffffu, s0, 1);
                float sr1 = __shfl_down_sync(0xffffffffu, s1, 1);
                float dr0 = __shfl_down_sync(0xffffffffu, d0, 1);
                float dr1 = __shfl_down_sync(0xffffffffu, d1, 1);
                if (isL) { sl0 = se0; sl1 = se1; dl0 = de0; dl1 = de1; }
                if (isR) { sr0 = se0; sr1 = se1; dr0 = de0; dr1 = de1; }

                xvt[e] = x1;
                xvb[e] = x2;
                gxt[e] = sr0 - sl0;
                gxb[e] = sr1 - sl1;
                gyt[e] = dl0 + 2.0f * d0 + dr0;
                gyb[e] = dl1 + 2.0f * d1 + dr1;
            }
            ft[0][cp] = pack2(xvt[0], xvt[1]);
            ft[1][cp] = pack2(gxt[0], gxt[1]);
            ft[2][cp] = pack2(gyt[0], gyt[1]);
            fb[0][cp] = pack2(xvb[0], xvb[1]);
            fb[1][cp] = pack2(gxb[0], gxb[1]);
            fb[2][cp] = pack2(gyb[0], gyb[1]);
        }

        // Conflict-free STS.128: 112 B stride -> quad index 7*lane mod 8, distinct
        char* rowt = smem + SM_A + pcol * PITCH_A;          // M-row = pcol (row h0)
        char* rowb = smem + SM_A + (128 + pcol) * PITCH_A;  // M-row = 128+pcol (row h0+1)
        #pragma unroll
        for (int f = 0; f < 3; f++) {
            *reinterpret_cast<uint4*>(rowt + f * 32 + c0 * 2) =
                make_uint4(ft[f][0], ft[f][1], ft[f][2], ft[f][3]);
            *reinterpret_cast<uint4*>(rowb + f * 32 + c0 * 2) =
                make_uint4(fb[f][0], fb[f][1], fb[f][2], fb[f][3]);
        }
    }
    __syncthreads();

    // ---------------- Phase 2: fused MLP (per warp: 32 M-rows) ----------------
    const int m0 = warp * 32;
    const int t  = lane & 3;
    const int g  = lane >> 2;

    // A fragments: 3 kt x 2 mt x 4 regs (loop-invariant; loaded once)
    uint32_t afr[3][2][4];
    #pragma unroll
    for (int kt = 0; kt < 3; kt++) {
        const uint32_t acol = kt * 32 + ((lane >> 4) << 4);
        ldsm_x4(afr[kt][0], sbase + SM_A + (m0 + (lane & 15)) * PITCH_A + acol);
        ldsm_x4(afr[kt][1], sbase + SM_A + (m0 + 16 + (lane & 15)) * PITCH_A + acol);
    }

    float c2[2][2][4];
    #pragma unroll
    for (int mt = 0; mt < 2; mt++)
        #pragma unroll
        for (int n2 = 0; n2 < 2; n2++)
            #pragma unroll
            for (int j = 0; j < 4; j++) c2[mt][n2][j] = 0.0f;

    #pragma unroll
    for (int hcj = 0; hcj < 8; hcj++) {       // 16 hidden units per chunk
        // bias pairs for this thread's output columns (fp32 exact)
        const float2 bA = *reinterpret_cast<const float2*>(
            smem + SM_BIAS + (hcj * 16 + t * 2) * 4);          // nt=0 cols
        const float2 bB = *reinterpret_cast<const float2*>(
            smem + SM_BIAS + (hcj * 16 + 8 + t * 2) * 4);      // nt=1 cols

        float c1[2][2][4];

        // kt = 0: D = A*B + bias  (no accumulator init MOVs)
        {
            uint32_t bfr[4];
            ldsm_x4(bfr, sbase + SM_W0 + (hcj * 16 + (lane & 15)) * PITCH_W0
                         + ((lane >> 4) << 4));
            mma16816_init(c1[0][0], afr[0][0], bfr[0], bfr[2], bA.x, bA.y);
            mma16816_init(c1[0][1], afr[0][1], bfr[0], bfr[2], bA.x, bA.y);
            mma16816_init(c1[1][0], afr[0][0], bfr[1], bfr[3], bB.x, bB.y);
            mma16816_init(c1[1][1], afr[0][1], bfr[1], bfr[3], bB.x, bB.y);
        }
        #pragma unroll
        for (int kt = 1; kt < 3; kt++) {
            uint32_t bfr[4];
            ldsm_x4(bfr, sbase + SM_W0 + (hcj * 16 + (lane & 15)) * PITCH_W0
                         + kt * 32 + ((lane >> 4) << 4));
            mma16816(c1[0][0], afr[kt][0], bfr[0], bfr[2]);
            mma16816(c1[0][1], afr[kt][1], bfr[0], bfr[2]);
            mma16816(c1[1][0], afr[kt][0], bfr[1], bfr[3]);
            mma16816(c1[1][1], afr[kt][1], bfr[1], bfr[3]);
        }

        // layer 2: one ldsm_x4 over W1 rows 0-15, k-cols [hcj*32 .. +16)
        uint32_t wfr[4];
        ldsm_x4(wfr, sbase + SM_W1 + (lane & 15) * PITCH_W1
                     + hcj * 32 + ((lane >> 4) << 4));
        #pragma unroll
        for (int mt = 0; mt < 2; mt++) {
            uint32_t a2[4];
            a2[0] = packrelu2(c1[0][mt][0], c1[0][mt][1]);
            a2[1] = packrelu2(c1[0][mt][2], c1[0][mt][3]);
            a2[2] = packrelu2(c1[1][mt][0], c1[1][mt][1]);
            a2[3] = packrelu2(c1[1][mt][2], c1[1][mt][3]);
            mma16816(c2[mt][0], a2, wfr[0], wfr[2]);
            mma16816(c2[mt][1], a2, wfr[1], wfr[3]);
        }
    }

    // ---------------- Stage update: [ch][260] layout (conflict-free STS.32) ----------------
    {
        float* s_upd = reinterpret_cast<float*>(smem + SM_UPD);
        #pragma unroll
        for (int mt = 0; mt < 2; mt++)
            #pragma unroll
            for (int n2 = 0; n2 < 2; n2++) {
                const int ch = n2 * 8 + t * 2;
                const int m  = m0 + mt * 16 + g;
                s_upd[ch * UPD_PITCH + m]           = c2[mt][n2][0];
                s_upd[(ch + 1) * UPD_PITCH + m]     = c2[mt][n2][1];
                s_upd[ch * UPD_PITCH + m + 8]       = c2[mt][n2][2];
                s_upd[(ch + 1) * UPD_PITCH + m + 8] = c2[mt][n2][3];
            }
    }
    __syncthreads();

    // ---------------- Phase 3: fully vectorized epilogue ----------------
    {
        const float* s_upd = reinterpret_cast<const float*>(smem + SM_UPD);
        const int q  = tid & 31;            // px quad
        const int r  = (tid >> 5) & 1;      // row within pair
        const int cg = tid >> 6;            // channel group (4 ch each)
        const int h  = h0 + r;
        const int pw = wpix + q * 4;

        const float4 u4 = *reinterpret_cast<const float4*>(
            ru + ((size_t)bb * HN + h) * WN + pw);
        const float m0f = (u4.x > 0.5f) ? 1.0f : 0.0f;
        const float m1f = (u4.y > 0.5f) ? 1.0f : 0.0f;
        const float m2f = (u4.z > 0.5f) ? 1.0f : 0.0f;
        const float m3f = (u4.w > 0.5f) ? 1.0f : 0.0f;

        #pragma unroll
        for (int i = 0; i < 4; i++) {
            const int c = cg * 4 + i;
            const float4 up = *reinterpret_cast<const float4*>(
                s_upd + c * UPD_PITCH + r * 128 + q * 4);
            const size_t gi = (((size_t)bb * CN + c) * HN + h) * WN + pw;
            const float4 xv = *reinterpret_cast<const float4*>(x + gi);
            float4 o;
            o.x = xv.x + up.x * m0f;
            o.y = xv.y + up.y * m1f;
            o.z = xv.z + up.z * m2f;
            o.w = xv.w + up.w * m3f;
            *reinterpret_cast<float4*>(out + gi) = o;
        }
    }
}

// ============================================================
// Launch
// ============================================================
extern "C" void kernel_launch(void* const* d_in, const int* in_sizes, int n_in,
                              void* d_out, int out_size) {
    (void)in_sizes; (void)n_in; (void)out_size;
    const float* x  = (const float*)d_in[0];
    const float* w0 = (const float*)d_in[1];
    const float* b0 = (const float*)d_in[2];
    const float* w1 = (const float*)d_in[3];
    const float* ru = (const float*)d_in[4];
    float* out = (float*)d_out;

    static bool attr_set = false;
    if (!attr_set) {
        cudaFuncSetAttribute(ca_mlp_kernel,
                             cudaFuncAttributeMaxDynamicSharedMemorySize, SM_TOTAL);
        attr_set = true;
    }

    const int grid = BN * (HN / 2) * (WN / TILE);   // 4096
    ca_mlp_kernel<<<grid, 256, SM_TOTAL>>>(x, w0, b0, w1, ru, out);
}